// round 12
// baseline (speedup 1.0000x reference)
#include <cstdint>
#include <cuda_runtime.h>
#include <cuda_bf16.h>
#include <cuda_fp16.h>
#include <math.h>
#include <float.h>

// Problem constants
#define Bc    2
#define Hh    64
#define Ww    160
#define DIMc  256
#define NHc   8
#define HDc   32
#define Nn    (Hh * Ww)       // 10240 tokens per batch
#define Mrows (Bc * Nn)       // 20480 total rows
#define SCALEF 0.17677669529663687f   // 32^-0.5

// Static scratch
__device__ uint32_t g_qh[Mrows * 128];    // q as half2, pre-scaled by SCALEF
__device__ uint32_t g_kh[Mrows * 128];    // k as half2
__device__ uint32_t g_vh[Mrows * 128];    // v as half2
__device__ uint2    g_xs[Mrows * 128];    // X pre-split bf16 hi/lo
__device__ uint2    g_hs[Mrows * 128];    // attn output pre-split bf16 hi/lo
__device__ uint32_t g_w [2 * 4 * 32768];  // W planes: [hi|lo][w][k][n/2] bf16x2
#define WLOFF_W 131072                    // word offset of lo planes
#define WLOFF_B 524288                    // byte offset of lo planes

// ---------------------------------------------------------------------------
// helpers
// ---------------------------------------------------------------------------
__device__ __forceinline__ uint32_t smem_to_u32(const void* smem_ptr) {
    uint32_t addr;
    asm("{ .reg .u64 tmp; cvta.to.shared.u64 tmp, %1; cvt.u32.u64 %0, tmp; }"
        : "=r"(addr) : "l"(smem_ptr));
    return addr;
}

__device__ __forceinline__ void bsplit(float x, float y, uint32_t& h, uint32_t& l) {
    asm("cvt.rn.bf16x2.f32 %0, %1, %2;" : "=r"(h) : "f"(y), "f"(x));
    float hx = __uint_as_float(h << 16);
    float hy = __uint_as_float(h & 0xffff0000u);
    asm("cvt.rn.bf16x2.f32 %0, %1, %2;" : "=r"(l) : "f"(y - hy), "f"(x - hx));
}

__device__ __forceinline__ uint32_t f2h2(float x, float y) {   // lo=x, hi=y
    uint32_t u;
    asm("cvt.rn.f16x2.f32 %0, %1, %2;" : "=r"(u) : "f"(y), "f"(x));
    return u;
}

__device__ __forceinline__ void mma_bf16(float* c, const uint32_t* a,
                                         uint32_t b0, uint32_t b1) {
    asm volatile(
        "mma.sync.aligned.m16n8k16.row.col.f32.bf16.bf16.f32 "
        "{%0,%1,%2,%3},{%4,%5,%6,%7},{%8,%9},{%0,%1,%2,%3};"
        : "+f"(c[0]), "+f"(c[1]), "+f"(c[2]), "+f"(c[3])
        : "r"(a[0]), "r"(a[1]), "r"(a[2]), "r"(a[3]), "r"(b0), "r"(b1));
}

__device__ __forceinline__ void ldsm_x4_t(uint32_t* r, uint32_t addr) {
    asm volatile(
        "ldmatrix.sync.aligned.m8n8.x4.trans.shared.b16 {%0,%1,%2,%3}, [%4];"
        : "=r"(r[0]), "=r"(r[1]), "=r"(r[2]), "=r"(r[3]) : "r"(addr));
}

#define CP16(dst, src) \
    asm volatile("cp.async.cg.shared.global [%0], [%1], 16;" :: "r"(dst), "l"(src))
#define CP_COMMIT() asm volatile("cp.async.commit_group;")
#define CP_WAIT(n)  asm volatile("cp.async.wait_group %0;" :: "n"(n))

// ---------------------------------------------------------------------------
// Merged conversion kernel: X pre-split + all 4 weights pre-split
// ---------------------------------------------------------------------------
#define XBLKS ((Mrows * 128) / 256)   // 10240

__global__ void __launch_bounds__(256)
conv_all(const float* __restrict__ x,
         const float* __restrict__ Wq, const float* __restrict__ Wk,
         const float* __restrict__ Wv, const float* __restrict__ Wp) {
    const int b = blockIdx.x;
    if (b < XBLKS) {
        size_t id = (size_t)b * 256 + threadIdx.x;
        float2 v = *reinterpret_cast<const float2*>(x + id * 2);
        uint32_t h, l;
        bsplit(v.x, v.y, h, l);
        g_xs[id] = make_uint2(h, l);
    } else {
        int id2 = (b - XBLKS) * 256 + threadIdx.x;   // 0 .. 131071
        int w = id2 >> 15;
        int id = id2 & 32767;
        const float* src = (w == 0) ? Wq : (w == 1) ? Wk : (w == 2) ? Wv : Wp;
        float2 v = *reinterpret_cast<const float2*>(src + (size_t)id * 2);
        uint32_t h, l;
        bsplit(v.x, v.y, h, l);
        g_w[w * 32768 + id] = h;
        g_w[WLOFF_W + w * 32768 + id] = l;
    }
}

// ---------------------------------------------------------------------------
// Persistent bf16x3 GEMM, cp.async, BK=64 stages, 2 buffers, cross-tile
// software pipelining.  BM=64, BN=128, 256 threads (8 warps, 32x32 warp tile).
// QKV=true: 1920 tiles (z in {q,k,v}), all epilogues fp16 packed.
// QKV=false (proj): 640 tiles, fp32 output.
// ---------------------------------------------------------------------------
#define A_ST   10240
#define BH_ST  8704
#define SUB    27648
#define STAGE  55296
#define SMEM_GEMM (2 * STAGE)
#define AROW_B 1024
#define GEMM_GRID 296

__device__ __forceinline__ void issue_stage(
    uint32_t base, int s, const char* Ag, const char* Wh,
    uint32_t ad0, uint32_t bd0)
{
#pragma unroll
    for (int c = 0; c < 2; c++) {
        const int g = s * 2 + c;
        const uint32_t sub = base + c * SUB;
        const char* a = Ag + g * 128;
        CP16(sub + ad0, a);
        CP16(sub + ad0 + 32 * 160, a + 32 * AROW_B);
        const char* wh = Wh + g * 16384;
        CP16(sub + bd0, wh);
        CP16(sub + bd0 + 16 * 272, wh + 16 * 512);
        const char* wl = Wh + WLOFF_B + g * 16384;
        CP16(sub + bd0 + BH_ST, wl);
        CP16(sub + bd0 + BH_ST + 16 * 272, wl + 16 * 512);
    }
    CP_COMMIT();
}

template<bool QKV>
__global__ void __launch_bounds__(256, 2)
gemm_persist(float* __restrict__ outF) {
    extern __shared__ char smem_c[];
    const uint32_t sb = smem_to_u32(smem_c);
    const int t    = threadIdx.x;
    const int warp = t >> 5;
    const int lane = t & 31;
    const int q    = lane >> 2;
    const int c4   = lane & 3;
    const int wm = (warp >> 2) * 32;
    const int wn = (warp & 3) * 32;
    const uint32_t ad0 = (uint32_t)((t >> 3) * 160 + (t & 7) * 16);
    const uint32_t bd0 = (uint32_t)(A_ST + (t >> 4) * 272 + (t & 15) * 16);

    const int NT = QKV ? 1920 : 640;
    const uint2* Asrc = QKV ? g_xs : g_hs;
    const uint32_t* whBase = QKV ? g_w : (g_w + 3 * 32768);

    // tile -> pointers
    const char* curA;
    const char* curW;
    int curTile;
    const char* nxtA;
    const char* nxtW;

    int tile = blockIdx.x;
    if (tile >= NT) return;
    {
        int z = tile / 640;
        int rem = tile - z * 640;
        int bn = (rem & 1) * 128;
        int bm = (rem >> 1) * 64;
        curA = (const char*)Asrc + (size_t)(bm + (t >> 3)) * AROW_B + (t & 7) * 16;
        curW = (const char*)(whBase + z * 32768)
             + (size_t)((t >> 4) * 256 + bn) * 2 + (t & 15) * 16;
        curTile = tile;
    }
    int nid = tile + GEMM_GRID;
    bool hn = nid < NT;
    if (hn) {
        int z = nid / 640;
        int rem = nid - z * 640;
        int bn = (rem & 1) * 128;
        int bm = (rem >> 1) * 64;
        nxtA = (const char*)Asrc + (size_t)(bm + (t >> 3)) * AROW_B + (t & 7) * 16;
        nxtW = (const char*)(whBase + z * 32768)
             + (size_t)((t >> 4) * 256 + bn) * 2 + (t & 15) * 16;
    } else {
        nxtA = curA; nxtW = curW;
    }

    issue_stage(sb, 0, curA, curW, ad0, bd0);

    for (;;) {
        float acc[2][4][4];
#pragma unroll
        for (int i = 0; i < 2; i++)
#pragma unroll
            for (int j = 0; j < 4; j++)
#pragma unroll
                for (int e = 0; e < 4; e++) acc[i][j][e] = 0.f;

#pragma unroll 1
        for (int s = 0; s < 4; s++) {
            if (s < 3) {
                issue_stage(sb + ((s + 1) & 1) * STAGE, s + 1, curA, curW, ad0, bd0);
                CP_WAIT(1);
            } else if (hn) {
                issue_stage(sb, 0, nxtA, nxtW, ad0, bd0);   // next tile stage 0 (parity 0)
                CP_WAIT(1);
            } else {
                CP_WAIT(0);
            }
            __syncthreads();

            const uint32_t bufb = sb + (s & 1) * STAGE;
            const char* bufc = smem_c + (s & 1) * STAGE;

#pragma unroll
            for (int c = 0; c < 2; c++) {
                const char* Ab = bufc + c * SUB;
                const uint32_t bhb = bufb + c * SUB + A_ST;
                const uint32_t blb = bhb + BH_ST;

#pragma unroll
                for (int k16 = 0; k16 < 2; k16++) {
                    uint32_t ah[2][4], al[2][4];
#pragma unroll
                    for (int mt = 0; mt < 2; mt++) {
                        const uint2* Ap = reinterpret_cast<const uint2*>(Ab)
                                        + (wm + mt * 16 + q) * 20 + k16 * 8 + c4;
                        uint2 u0 = Ap[0];
                        uint2 u1 = Ap[160];
                        uint2 u2 = Ap[4];
                        uint2 u3 = Ap[164];
                        ah[mt][0] = u0.x; al[mt][0] = u0.y;
                        ah[mt][1] = u1.x; al[mt][1] = u1.y;
                        ah[mt][2] = u2.x; al[mt][2] = u2.y;
                        ah[mt][3] = u3.x; al[mt][3] = u3.y;
                    }
                    uint32_t bh[2][4], bl[2][4];
#pragma unroll
                    for (int nc = 0; nc < 2; nc++) {
                        uint32_t off = (uint32_t)((k16 * 16 + (lane & 15)) * 272
                                      + (wn + nc * 16 + ((lane >> 4) << 3)) * 2);
                        ldsm_x4_t(bh[nc], bhb + off);
                        ldsm_x4_t(bl[nc], blb + off);
                    }
#pragma unroll
                    for (int mt = 0; mt < 2; mt++)
#pragma unroll
                        for (int n8 = 0; n8 < 4; n8++) {
                            const int nc = n8 >> 1, jj = (n8 & 1) * 2;
                            mma_bf16(acc[mt][n8], ah[mt], bh[nc][jj], bh[nc][jj + 1]);
                            mma_bf16(acc[mt][n8], ah[mt], bl[nc][jj], bl[nc][jj + 1]);
                            mma_bf16(acc[mt][n8], al[mt], bh[nc][jj], bh[nc][jj + 1]);
                        }
                }
            }
            __syncthreads();
        }

        // epilogue for curTile
        {
            int z = curTile / 640;
            int rem = curTile - z * 640;
            int bn = (rem & 1) * 128;
            int bm = (rem >> 1) * 64;
            if (QKV) {
                uint32_t* Ch = (z == 0) ? g_qh : (z == 1) ? g_kh : g_vh;
                const float sc = (z == 0) ? SCALEF : 1.f;
#pragma unroll
                for (int mt = 0; mt < 2; mt++)
#pragma unroll
                    for (int n8 = 0; n8 < 4; n8++) {
                        const int gr0 = bm + wm + mt * 16 + q;
                        const int gc  = bn + wn + n8 * 8 + 2 * c4;
                        Ch[(size_t)gr0 * 128 + (gc >> 1)] =
                            f2h2(acc[mt][n8][0] * sc, acc[mt][n8][1] * sc);
                        Ch[(size_t)(gr0 + 8) * 128 + (gc >> 1)] =
                            f2h2(acc[mt][n8][2] * sc, acc[mt][n8][3] * sc);
                    }
            } else {
#pragma unroll
                for (int mt = 0; mt < 2; mt++)
#pragma unroll
                    for (int n8 = 0; n8 < 4; n8++) {
                        const int gr0 = bm + wm + mt * 16 + q;
                        const int gc  = bn + wn + n8 * 8 + 2 * c4;
                        *reinterpret_cast<float2*>(outF + (size_t)gr0 * DIMc + gc) =
                            make_float2(acc[mt][n8][0], acc[mt][n8][1]);
                        *reinterpret_cast<float2*>(outF + (size_t)(gr0 + 8) * DIMc + gc) =
                            make_float2(acc[mt][n8][2], acc[mt][n8][3]);
                    }
            }
        }

        if (!hn) break;
        curA = nxtA; curW = nxtW; curTile = nid;
        nid += GEMM_GRID;
        hn = nid < NT;
        if (hn) {
            int z = nid / 640;
            int rem = nid - z * 640;
            int bn = (rem & 1) * 128;
            int bm = (rem >> 1) * 64;
            nxtA = (const char*)Asrc + (size_t)(bm + (t >> 3)) * AROW_B + (t & 7) * 16;
            nxtW = (const char*)(whBase + z * 32768)
                 + (size_t)((t >> 4) * 256 + bn) * 2 + (t & 15) * 16;
        }
    }
}

// ---------------------------------------------------------------------------
// Attention: fp16 Q/K/V, 4 dims per lane, 4 position-groups per warp.
// ---------------------------------------------------------------------------
__global__ void __launch_bounds__(256, 6)
attn_kernel(const float* __restrict__ mo) {
    const int r = blockIdx.x;
    const int bofs = (r >= Nn) ? Nn : 0;
    const int hd = threadIdx.x >> 5;      // head
    const int lane = threadIdx.x & 31;
    const int g  = lane & 7;              // dim group (4 dims)
    const int sd = lane >> 3;             // window column 0..3

    float2 o2 = *reinterpret_cast<const float2*>(mo + (size_t)r * 2);
    float ox = fminf(fmaxf(o2.x, 1.0f), (float)(Ww - 2) - 0.001f);
    float oy = fminf(fmaxf(o2.y, 1.0f), (float)(Hh - 2) - 0.001f);
    const float mx = floorf(ox), my = floorf(oy);
    const float fx = ox - mx,   fy = oy - my;

    const int ibase = bofs + ((int)my - 1) * Ww + ((int)mx - 1);

    // q: 4 dims fp16 (pre-scaled by SCALEF at GEMM epilogue)
    uint2 qq = *reinterpret_cast<const uint2*>(
        g_qh + (size_t)r * 128 + hd * 16 + g * 2);
    const float2 q01 = __half22float2(*reinterpret_cast<const __half2*>(&qq.x));
    const float2 q23 = __half22float2(*reinterpret_cast<const __half2*>(&qq.y));

    const uint32_t* kp = g_kh + (size_t)ibase * 128 + hd * 16 + g * 2;
    const uint32_t* vp = g_vh + (size_t)ibase * 128 + hd * 16 + g * 2;

    int roff[4];
    float part[4];
#pragma unroll
    for (int i = 0; i < 4; i++) {
        roff[i] = (i * Ww + sd) * 128;
        uint2 kk = *reinterpret_cast<const uint2*>(kp + roff[i]);
        float2 k01 = __half22float2(*reinterpret_cast<const __half2*>(&kk.x));
        float2 k23 = __half22float2(*reinterpret_cast<const __half2*>(&kk.y));
        part[i] = q01.x * k01.x + q01.y * k01.y + q23.x * k23.x + q23.y * k23.y;
    }

    // 4-value butterfly within 8-lane groups (offsets 4,2,1)
    float u2[2];
    {
        const bool hb = (lane & 4) != 0;
#pragma unroll
        for (int j = 0; j < 2; j++) {
            float keep = hb ? part[j + 2] : part[j];
            float send = hb ? part[j] : part[j + 2];
            u2[j] = keep + __shfl_xor_sync(0xffffffffu, send, 4);
        }
    }
    float u1;
    {
        const bool hb = (lane & 2) != 0;
        float keep = hb ? u2[1] : u2[0];
        float send = hb ? u2[0] : u2[1];
        u1 = keep + __shfl_xor_sync(0xffffffffu, send, 2);
    }
    const float s = u1 + __shfl_xor_sync(0xffffffffu, u1, 1);
    // lane holds score of position a = 4*i_mine + sd, i_mine = (lane>>1)&3

    const int i_mine = (lane >> 1) & 3;
    const float wxv = (sd == 0) ? (1.f - fx) : ((sd == 3) ? fx : 1.f);
    const float wyv = (i_mine == 0) ? (1.f - fy) : ((i_mine == 3) ? fy : 1.f);
    const float bw = wxv * wyv;

    float mval = s;
#pragma unroll
    for (int o = 16; o > 0; o >>= 1)
        mval = fmaxf(mval, __shfl_xor_sync(0xffffffffu, mval, o));
    const float e = __expf(s - mval) * bw;
    float se = e;
#pragma unroll
    for (int o = 16; o > 0; o >>= 1)
        se += __shfl_xor_sync(0xffffffffu, se, o);
    const float p = __fdividef(e, 0.5f * se);

    float f0 = 0.f, f1 = 0.f, f2 = 0.f, f3 = 0.f;
#pragma unroll
    for (int i = 0; i < 4; i++) {
        uint2 vv = *reinterpret_cast<const uint2*>(vp + roff[i]);
        float2 v01 = __half22float2(*reinterpret_cast<const __half2*>(&vv.x));
        float2 v23 = __half22float2(*reinterpret_cast<const __half2*>(&vv.y));
        float pa = __shfl_sync(0xffffffffu, p, (lane & 24) | (i << 1));
        f0 += pa * v01.x;
        f1 += pa * v01.y;
        f2 += pa * v23.x;
        f3 += pa * v23.y;
    }
#pragma unroll
    for (int o = 8; o <= 16; o <<= 1) {
        f0 += __shfl_xor_sync(0xffffffffu, f0, o);
        f1 += __shfl_xor_sync(0xffffffffu, f1, o);
        f2 += __shfl_xor_sync(0xffffffffu, f2, o);
        f3 += __shfl_xor_sync(0xffffffffu, f3, o);
    }

    if (sd == 0) {
        uint32_t h0, l0, h1, l1;
        bsplit(f0, f1, h0, l0);
        bsplit(f2, f3, h1, l1);
        *reinterpret_cast<uint4*>(g_hs + (size_t)r * 128 + hd * 16 + g * 2) =
            make_uint4(h0, l0, h1, l1);
    }
}

// ---------------------------------------------------------------------------
extern "C" void kernel_launch(void* const* d_in, const int* in_sizes, int n_in,
                              void* d_out, int out_size) {
    const float* x  = (const float*)d_in[0];
    const float* mo = (const float*)d_in[1];
    const float* Wq = (const float*)d_in[2];
    const float* Wk = (const float*)d_in[3];
    const float* Wv = (const float*)d_in[4];
    const float* Wp = (const float*)d_in[5];
    float* out = (float*)d_out;

    cudaFuncSetAttribute(gemm_persist<true>,
                         cudaFuncAttributeMaxDynamicSharedMemorySize, SMEM_GEMM);
    cudaFuncSetAttribute(gemm_persist<false>,
                         cudaFuncAttributeMaxDynamicSharedMemorySize, SMEM_GEMM);

    conv_all<<<XBLKS + 512, 256>>>(x, Wq, Wk, Wv, Wp);
    gemm_persist<true><<<GEMM_GRID, 256, SMEM_GEMM>>>(nullptr);
    attn_kernel<<<Mrows, 256>>>(mo);
    gemm_persist<false><<<GEMM_GRID, 256, SMEM_GEMM>>>(out);
}

// round 13
// speedup vs baseline: 1.2775x; 1.2775x over previous
#include <cstdint>
#include <cuda_runtime.h>
#include <cuda_fp16.h>
#include <math.h>
#include <float.h>

// Problem constants
#define Bc    2
#define Hh    64
#define Ww    160
#define DIMc  256
#define NHc   8
#define HDc   32
#define Nn    (Hh * Ww)       // 10240 tokens per batch
#define Mrows (Bc * Nn)       // 20480 total rows
#define SCALEF 0.17677669529663687f   // 32^-0.5

// Static scratch (all activations fp16, packed half2)
__device__ uint32_t g_qh[Mrows * 128];    // q, pre-scaled by SCALEF
__device__ uint32_t g_kh[Mrows * 128];
__device__ uint32_t g_vh[Mrows * 128];
__device__ uint32_t g_xh[Mrows * 128];    // X as fp16
__device__ uint32_t g_hf[Mrows * 128];    // attn output as fp16
__device__ uint32_t g_wf[2 * 4 * 32768];  // W fp16 planes: [hi|lo][w][k][n/2]
#define WLOFF_B 524288                    // byte offset of lo planes

// ---------------------------------------------------------------------------
// helpers
// ---------------------------------------------------------------------------
__device__ __forceinline__ uint32_t smem_to_u32(const void* smem_ptr) {
    uint32_t addr;
    asm("{ .reg .u64 tmp; cvta.to.shared.u64 tmp, %1; cvt.u32.u64 %0, tmp; }"
        : "=r"(addr) : "l"(smem_ptr));
    return addr;
}

__device__ __forceinline__ uint32_t f2h2(float x, float y) {   // lo=x, hi=y
    uint32_t u;
    asm("cvt.rn.f16x2.f32 %0, %1, %2;" : "=r"(u) : "f"(y), "f"(x));
    return u;
}

__device__ __forceinline__ void mma_f16(float* c, const uint32_t* a,
                                        uint32_t b0, uint32_t b1) {
    asm volatile(
        "mma.sync.aligned.m16n8k16.row.col.f32.f16.f16.f32 "
        "{%0,%1,%2,%3},{%4,%5,%6,%7},{%8,%9},{%0,%1,%2,%3};"
        : "+f"(c[0]), "+f"(c[1]), "+f"(c[2]), "+f"(c[3])
        : "r"(a[0]), "r"(a[1]), "r"(a[2]), "r"(a[3]), "r"(b0), "r"(b1));
}

__device__ __forceinline__ void ldsm_x4(uint32_t* r, uint32_t addr) {
    asm volatile(
        "ldmatrix.sync.aligned.m8n8.x4.shared.b16 {%0,%1,%2,%3}, [%4];"
        : "=r"(r[0]), "=r"(r[1]), "=r"(r[2]), "=r"(r[3]) : "r"(addr));
}

__device__ __forceinline__ void ldsm_x4_t(uint32_t* r, uint32_t addr) {
    asm volatile(
        "ldmatrix.sync.aligned.m8n8.x4.trans.shared.b16 {%0,%1,%2,%3}, [%4];"
        : "=r"(r[0]), "=r"(r[1]), "=r"(r[2]), "=r"(r[3]) : "r"(addr));
}

#define CP16(dst, src) \
    asm volatile("cp.async.cg.shared.global [%0], [%1], 16;" :: "r"(dst), "l"(src))
#define CP_COMMIT() asm volatile("cp.async.commit_group;")
#define CP_WAIT(n)  asm volatile("cp.async.wait_group %0;" :: "n"(n))

// ---------------------------------------------------------------------------
// Conversion: X -> fp16, W -> fp16 hi/lo planes
// ---------------------------------------------------------------------------
#define XBLKS ((Mrows * 128) / 256)   // 10240

__global__ void __launch_bounds__(256)
conv_all(const float* __restrict__ x,
         const float* __restrict__ Wq, const float* __restrict__ Wk,
         const float* __restrict__ Wv, const float* __restrict__ Wp) {
    const int b = blockIdx.x;
    if (b < XBLKS) {
        size_t id = (size_t)b * 256 + threadIdx.x;
        float2 v = *reinterpret_cast<const float2*>(x + id * 2);
        g_xh[id] = f2h2(v.x, v.y);
    } else {
        int id2 = (b - XBLKS) * 256 + threadIdx.x;   // 0 .. 131071
        int w = id2 >> 15;
        int id = id2 & 32767;
        const float* src = (w == 0) ? Wq : (w == 1) ? Wk : (w == 2) ? Wv : Wp;
        float2 v = *reinterpret_cast<const float2*>(src + (size_t)id * 2);
        uint32_t h = f2h2(v.x, v.y);
        __half2 hh = *reinterpret_cast<__half2*>(&h);
        float2 hf = __half22float2(hh);
        g_wf[w * 32768 + id] = h;
        g_wf[131072 + w * 32768 + id] = f2h2(v.x - hf.x, v.y - hf.y);
    }
}

// ---------------------------------------------------------------------------
// fp16x2 GEMM: C = A_fp16 @ (Whi + Wlo).  BM=64, BN=128, BK=64 stages
// (2 x k32 sub-chunks), 2 buffers, cp.async.  256 threads, 8 warps (2m x 4n).
// A smem: [m][k] fp16, row stride 80 B (ldmatrix non-trans, conflict-free).
// B smem: hi/lo [k][n] fp16, row stride 272 B (ldmatrix trans).
// ---------------------------------------------------------------------------
#define A_ST   5120              // 64 rows * 80 B
#define BH_ST  8704              // 32 rows * 272 B
#define SUB    22528             // A_ST + 2*BH_ST
#define STAGE  45056
#define SMEM_GEMM (2 * STAGE)    // 90112
#define AROW_B 512               // gmem fp16 activation row bytes

__device__ __forceinline__ void issue_stage(
    uint32_t base, int s, const char* Ag, const char* Wh,
    uint32_t ad0, uint32_t bd0)
{
#pragma unroll
    for (int c = 0; c < 2; c++) {
        const int g = s * 2 + c;                 // k32 chunk 0..7
        const uint32_t sub = base + c * SUB;
        CP16(sub + ad0, Ag + g * 64);
        const char* wh = Wh + g * 16384;         // 32 k-rows * 512 B
        CP16(sub + bd0, wh);
        CP16(sub + bd0 + 16 * 272, wh + 16 * 512);
        const char* wl = Wh + WLOFF_B + g * 16384;
        CP16(sub + bd0 + BH_ST, wl);
        CP16(sub + bd0 + BH_ST + 16 * 272, wl + 16 * 512);
    }
    CP_COMMIT();
}

__device__ __forceinline__ void gemm_body(const uint32_t* __restrict__ Asrc,
                                          const uint32_t* __restrict__ Wplane,
                                          float* __restrict__ Cf,
                                          uint32_t* __restrict__ Ch,
                                          float qscale) {
    extern __shared__ char smem_c[];
    const uint32_t sb = smem_to_u32(smem_c);
    const int t    = threadIdx.x;
    const int warp = t >> 5;
    const int lane = t & 31;
    const int q    = lane >> 2;
    const int c4   = lane & 3;
    const int bm = blockIdx.y * 64;
    const int bn = blockIdx.x * 128;
    const int wm = (warp >> 2) * 32;
    const int wn = (warp & 3) * 32;

    // staging: A 1 CP16/thread/k32 (row t>>2, 16B col t&3)
    const char* Ag = (const char*)Asrc + (size_t)(bm + (t >> 2)) * AROW_B + (t & 3) * 16;
    // B: 2 CP16/plane/thread (rows t>>4, t>>4+16; 16B col t&15)
    const char* Wh = (const char*)Wplane + (size_t)(t >> 4) * 512 + bn * 2 + (t & 15) * 16;
    const uint32_t ad0 = (uint32_t)((t >> 2) * 80 + (t & 3) * 16);
    const uint32_t bd0 = (uint32_t)(A_ST + (t >> 4) * 272 + (t & 15) * 16);

    float acc[2][4][4];
#pragma unroll
    for (int i = 0; i < 2; i++)
#pragma unroll
        for (int j = 0; j < 4; j++)
#pragma unroll
            for (int e = 0; e < 4; e++) acc[i][j][e] = 0.f;

    issue_stage(sb, 0, Ag, Wh, ad0, bd0);

#pragma unroll 1
    for (int s = 0; s < 4; s++) {
        if (s < 3) {
            issue_stage(sb + ((s + 1) & 1) * STAGE, s + 1, Ag, Wh, ad0, bd0);
            CP_WAIT(1);
        } else {
            CP_WAIT(0);
        }
        __syncthreads();

        const uint32_t bufb = sb + (s & 1) * STAGE;

#pragma unroll
        for (int c = 0; c < 2; c++) {
            const uint32_t abase = bufb + c * SUB;
            const uint32_t bhb = abase + A_ST;
            const uint32_t blb = bhb + BH_ST;

#pragma unroll
            for (int k16 = 0; k16 < 2; k16++) {
                uint32_t a[2][4];
#pragma unroll
                for (int mt = 0; mt < 2; mt++) {
                    ldsm_x4(a[mt], abase + (wm + mt * 16 + (lane & 15)) * 80
                                 + k16 * 32 + (lane >> 4) * 16);
                }
                uint32_t bh[2][4], bl[2][4];
#pragma unroll
                for (int nc = 0; nc < 2; nc++) {
                    uint32_t off = (uint32_t)((k16 * 16 + (lane & 15)) * 272
                                  + (wn + nc * 16 + ((lane >> 4) << 3)) * 2);
                    ldsm_x4_t(bh[nc], bhb + off);
                    ldsm_x4_t(bl[nc], blb + off);
                }
#pragma unroll
                for (int mt = 0; mt < 2; mt++)
#pragma unroll
                    for (int n8 = 0; n8 < 4; n8++) {
                        const int nc = n8 >> 1, jj = (n8 & 1) * 2;
                        mma_f16(acc[mt][n8], a[mt], bh[nc][jj], bh[nc][jj + 1]);
                        mma_f16(acc[mt][n8], a[mt], bl[nc][jj], bl[nc][jj + 1]);
                    }
            }
        }
        __syncthreads();
    }

    // epilogue
    if (Ch) {
#pragma unroll
        for (int mt = 0; mt < 2; mt++)
#pragma unroll
            for (int n8 = 0; n8 < 4; n8++) {
                const int gr0 = bm + wm + mt * 16 + q;
                const int gc  = bn + wn + n8 * 8 + 2 * c4;
                Ch[(size_t)gr0 * 128 + (gc >> 1)] =
                    f2h2(acc[mt][n8][0] * qscale, acc[mt][n8][1] * qscale);
                Ch[(size_t)(gr0 + 8) * 128 + (gc >> 1)] =
                    f2h2(acc[mt][n8][2] * qscale, acc[mt][n8][3] * qscale);
            }
    } else {
#pragma unroll
        for (int mt = 0; mt < 2; mt++)
#pragma unroll
            for (int n8 = 0; n8 < 4; n8++) {
                const int gr0 = bm + wm + mt * 16 + q;
                const int gc  = bn + wn + n8 * 8 + 2 * c4;
                *reinterpret_cast<float2*>(Cf + (size_t)gr0 * DIMc + gc) =
                    make_float2(acc[mt][n8][0], acc[mt][n8][1]);
                *reinterpret_cast<float2*>(Cf + (size_t)(gr0 + 8) * DIMc + gc) =
                    make_float2(acc[mt][n8][2], acc[mt][n8][3]);
            }
    }
}

__global__ void __launch_bounds__(256, 2)
gemm_qkv() {
    const int z = blockIdx.z;
    uint32_t* Ch = (z == 0) ? g_qh : (z == 1) ? g_kh : g_vh;
    gemm_body(g_xh, g_wf + z * 32768, nullptr, Ch, (z == 0) ? SCALEF : 1.f);
}

__global__ void __launch_bounds__(256, 2)
gemm_proj(float* __restrict__ out) {
    gemm_body(g_hf, g_wf + 3 * 32768, out, nullptr, 1.f);
}

// ---------------------------------------------------------------------------
// Attention: fp16 Q/K/V, 4 dims per lane, 4 position-groups per warp.
// ---------------------------------------------------------------------------
__global__ void __launch_bounds__(256, 6)
attn_kernel(const float* __restrict__ mo) {
    const int r = blockIdx.x;
    const int bofs = (r >= Nn) ? Nn : 0;
    const int hd = threadIdx.x >> 5;
    const int lane = threadIdx.x & 31;
    const int g  = lane & 7;              // dim group (4 dims)
    const int sd = lane >> 3;             // window column 0..3

    float2 o2 = *reinterpret_cast<const float2*>(mo + (size_t)r * 2);
    float ox = fminf(fmaxf(o2.x, 1.0f), (float)(Ww - 2) - 0.001f);
    float oy = fminf(fmaxf(o2.y, 1.0f), (float)(Hh - 2) - 0.001f);
    const float mx = floorf(ox), my = floorf(oy);
    const float fx = ox - mx,   fy = oy - my;

    const int ibase = bofs + ((int)my - 1) * Ww + ((int)mx - 1);

    uint2 qq = *reinterpret_cast<const uint2*>(
        g_qh + (size_t)r * 128 + hd * 16 + g * 2);
    const float2 q01 = __half22float2(*reinterpret_cast<const __half2*>(&qq.x));
    const float2 q23 = __half22float2(*reinterpret_cast<const __half2*>(&qq.y));

    const uint32_t* kp = g_kh + (size_t)ibase * 128 + hd * 16 + g * 2;
    const uint32_t* vp = g_vh + (size_t)ibase * 128 + hd * 16 + g * 2;

    int roff[4];
    float part[4];
#pragma unroll
    for (int i = 0; i < 4; i++) {
        roff[i] = (i * Ww + sd) * 128;
        uint2 kk = *reinterpret_cast<const uint2*>(kp + roff[i]);
        float2 k01 = __half22float2(*reinterpret_cast<const __half2*>(&kk.x));
        float2 k23 = __half22float2(*reinterpret_cast<const __half2*>(&kk.y));
        part[i] = q01.x * k01.x + q01.y * k01.y + q23.x * k23.x + q23.y * k23.y;
    }

    float u2[2];
    {
        const bool hb = (lane & 4) != 0;
#pragma unroll
        for (int j = 0; j < 2; j++) {
            float keep = hb ? part[j + 2] : part[j];
            float send = hb ? part[j] : part[j + 2];
            u2[j] = keep + __shfl_xor_sync(0xffffffffu, send, 4);
        }
    }
    float u1;
    {
        const bool hb = (lane & 2) != 0;
        float keep = hb ? u2[1] : u2[0];
        float send = hb ? u2[0] : u2[1];
        u1 = keep + __shfl_xor_sync(0xffffffffu, send, 2);
    }
    const float s = u1 + __shfl_xor_sync(0xffffffffu, u1, 1);

    const int i_mine = (lane >> 1) & 3;
    const float wxv = (sd == 0) ? (1.f - fx) : ((sd == 3) ? fx : 1.f);
    const float wyv = (i_mine == 0) ? (1.f - fy) : ((i_mine == 3) ? fy : 1.f);
    const float bw = wxv * wyv;

    float mval = s;
#pragma unroll
    for (int o = 16; o > 0; o >>= 1)
        mval = fmaxf(mval, __shfl_xor_sync(0xffffffffu, mval, o));
    const float e = __expf(s - mval) * bw;
    float se = e;
#pragma unroll
    for (int o = 16; o > 0; o >>= 1)
        se += __shfl_xor_sync(0xffffffffu, se, o);
    const float p = __fdividef(e, 0.5f * se);

    float f0 = 0.f, f1 = 0.f, f2 = 0.f, f3 = 0.f;
#pragma unroll
    for (int i = 0; i < 4; i++) {
        uint2 vv = *reinterpret_cast<const uint2*>(vp + roff[i]);
        float2 v01 = __half22float2(*reinterpret_cast<const __half2*>(&vv.x));
        float2 v23 = __half22float2(*reinterpret_cast<const __half2*>(&vv.y));
        float pa = __shfl_sync(0xffffffffu, p, (lane & 24) | (i << 1));
        f0 += pa * v01.x;
        f1 += pa * v01.y;
        f2 += pa * v23.x;
        f3 += pa * v23.y;
    }
#pragma unroll
    for (int o = 8; o <= 16; o <<= 1) {
        f0 += __shfl_xor_sync(0xffffffffu, f0, o);
        f1 += __shfl_xor_sync(0xffffffffu, f1, o);
        f2 += __shfl_xor_sync(0xffffffffu, f2, o);
        f3 += __shfl_xor_sync(0xffffffffu, f3, o);
    }

    if (sd == 0) {
        uint2 o;
        o.x = f2h2(f0, f1);
        o.y = f2h2(f2, f3);
        *reinterpret_cast<uint2*>(g_hf + (size_t)r * 128 + hd * 16 + g * 2) = o;
    }
}

// ---------------------------------------------------------------------------
extern "C" void kernel_launch(void* const* d_in, const int* in_sizes, int n_in,
                              void* d_out, int out_size) {
    const float* x  = (const float*)d_in[0];
    const float* mo = (const float*)d_in[1];
    const float* Wq = (const float*)d_in[2];
    const float* Wk = (const float*)d_in[3];
    const float* Wv = (const float*)d_in[4];
    const float* Wp = (const float*)d_in[5];
    float* out = (float*)d_out;

    cudaFuncSetAttribute(gemm_qkv, cudaFuncAttributeMaxDynamicSharedMemorySize, SMEM_GEMM);
    cudaFuncSetAttribute(gemm_proj, cudaFuncAttributeMaxDynamicSharedMemorySize, SMEM_GEMM);

    conv_all<<<XBLKS + 512, 256>>>(x, Wq, Wk, Wv, Wp);
    gemm_qkv<<<dim3(2, Mrows / 64, 3), 256, SMEM_GEMM>>>();
    attn_kernel<<<Mrows, 256>>>(mo);
    gemm_proj<<<dim3(2, Mrows / 64), 256, SMEM_GEMM>>>(out);
}